// round 15
// baseline (speedup 1.0000x reference)
#include <cuda_runtime.h>
#include <cstdint>

// Problem constants (fixed by the reference)
#define B_ 32
#define D_ 64
#define T_ 4096
#define K_ 512
#define N_ (B_ * T_)        // 131072 tokens
#define NQ_ (B_ * D_ * T_)  // 8388608 quantized elements
#define THREADS_ 384
#define CHTOK_ 768          // tokens per chunk (2 per thread)
#define NCHUNK_ 171         // ceil(131072 / 768); last chunk has 512 valid
#define NBLK_ 148           // persistent blocks (1/SM)

// Scratch (device globals: no allocation allowed)
__device__ unsigned int g_maxz_bits;
__device__ unsigned int g_maxc_bits;
__device__ float        g_cbnorm[K_];
__device__ int2         g_cnsc[K_];            // (cn_int - ch, 2*ch), ch = ceil(sc/2)
__device__ __align__(16) int g_cbimg[K_ * 16];
__device__ float        g_partial[256];        // 171 used; rest stay 0
__device__ unsigned int g_count;
__device__ unsigned int g_chunk;

// ---------------------------------------------------------------------------
// prep 0: global max |z|
// ---------------------------------------------------------------------------
__global__ void prep_z_kernel(const float* __restrict__ z) {
    const float4* z4 = reinterpret_cast<const float4*>(z);
    float m = 0.0f;
    for (int j = blockIdx.x * blockDim.x + threadIdx.x; j < NQ_ / 4;
         j += gridDim.x * blockDim.x) {
        float4 v = z4[j];
        m = fmaxf(m, fmaxf(fmaxf(fabsf(v.x), fabsf(v.y)),
                           fmaxf(fabsf(v.z), fabsf(v.w))));
    }
#pragma unroll
    for (int o = 16; o > 0; o >>= 1) m = fmaxf(m, __shfl_xor_sync(0xffffffffu, m, o));
    if ((threadIdx.x & 31) == 0) atomicMax(&g_maxz_bits, __float_as_uint(m));
}

// ---------------------------------------------------------------------------
// fused codebook prep: single block, 512 threads (one code each).
// norms in canonical fmaf order (proven rel_err = 0.0); maxc via shared-max
// (same value as atomicMax); then int8 image + (cn_int - ch, 2*ch).
// ---------------------------------------------------------------------------
__global__ void prep_cb_kernel(const float* __restrict__ cb) {
    __shared__ float s_red[512];
    const int k = threadIdx.x;                  // 0..511
    const float* r = cb + k * D_;
    float a = 0.0f, mx = 0.0f;
#pragma unroll
    for (int i = 0; i < D_; ++i) {
        a = fmaf(r[i], r[i], a);
        mx = fmaxf(mx, fabsf(r[i]));
    }
    g_cbnorm[k] = a;
    s_red[k] = mx;
    __syncthreads();
    for (int st = 256; st > 0; st >>= 1) {
        if (k < st) s_red[k] = fmaxf(s_red[k], s_red[k + st]);
        __syncthreads();
    }
    const float maxc = s_red[0];
    if (k == 0) g_maxc_bits = __float_as_uint(maxc);

    const float maxz = __uint_as_float(g_maxz_bits);
    const float inv_sc = (maxc > 0.0f) ? 127.0f / maxc : 0.0f;
    int sa = 0;
#pragma unroll
    for (int j = 0; j < 16; ++j) {
        int b0 = min(127, max(-127, __float2int_rn(r[4 * j + 0] * inv_sc)));
        int b1 = min(127, max(-127, __float2int_rn(r[4 * j + 1] * inv_sc)));
        int b2 = min(127, max(-127, __float2int_rn(r[4 * j + 2] * inv_sc)));
        int b3 = min(127, max(-127, __float2int_rn(r[4 * j + 3] * inv_sc)));
        sa += abs(b0) + abs(b1) + abs(b2) + abs(b3);
        g_cbimg[k * 16 + j] = (b0 & 0xFF) | ((b1 & 0xFF) << 8) |
                              ((b2 & 0xFF) << 16) | ((b3 & 0xFF) << 24);
    }
    const float denom = 2.0f * (maxz * (1.0f / 127.0f)) * (maxc * (1.0f / 127.0f));
    float v = (denom > 0.0f) ? a / denom : 0.0f;
    int cni = __float2int_rn(fminf(fmaxf(v, -2.0e9f), 2.0e9f));
    int ch  = (sa + 1) >> 1;                    // ceil(sc/2): conservative
    g_cnsc[k] = make_int2(cni - ch, 2 * ch);
}

// ---------------------------------------------------------------------------
// smem layout. CBF rows 272B: 64 fp32 (0..255) + int2(cnlo,2ch)@256 + cn@264.
// ---------------------------------------------------------------------------
#define SM_IMG   0                            // 2048 int4        =  32768
#define SM_CBF   32768                        // 512 * 272        = 139264
#define SM_MASK  172032                       // 16*768 uint      =  49152
#define SM_WSUM  221184                       // 12 float (+pad)  =     64
#define SM_RD    221248                       // 256 double       =   2048
#define SM_LAST  223296                       // int              =      4
#define SM_CHNK  223300                       // int (+pad)       =     12
#define SM_TOT   223312

// dual-token dp4a score block: s0/s1 = (cn_int - ch) - idot (seeded)
#define DP4A_SCORE2(k, sOut0, sOut1) do {                                 \
    int4 c0 = s_img[4 * (k) + 0], c1 = s_img[4 * (k) + 1];                \
    int4 c2 = s_img[4 * (k) + 2], c3 = s_img[4 * (k) + 3];                \
    int2 cs = *reinterpret_cast<const int2*>(sm + SM_CBF + (k) * 272 + 256); \
    int a0 = cs.x, a1 = 0, a2 = 0, a3 = 0;                                \
    int b0 = cs.x, b1 = 0, b2 = 0, b3 = 0;                                \
    a0 = __dp4a(zp0[0],  c0.x, a0);  b0 = __dp4a(zp1[0],  c0.x, b0);      \
    a1 = __dp4a(zp0[1],  c0.y, a1);  b1 = __dp4a(zp1[1],  c0.y, b1);      \
    a2 = __dp4a(zp0[2],  c0.z, a2);  b2 = __dp4a(zp1[2],  c0.z, b2);      \
    a3 = __dp4a(zp0[3],  c0.w, a3);  b3 = __dp4a(zp1[3],  c0.w, b3);      \
    a0 = __dp4a(zp0[4],  c1.x, a0);  b0 = __dp4a(zp1[4],  c1.x, b0);      \
    a1 = __dp4a(zp0[5],  c1.y, a1);  b1 = __dp4a(zp1[5],  c1.y, b1);      \
    a2 = __dp4a(zp0[6],  c1.z, a2);  b2 = __dp4a(zp1[6],  c1.z, b2);      \
    a3 = __dp4a(zp0[7],  c1.w, a3);  b3 = __dp4a(zp1[7],  c1.w, b3);      \
    a0 = __dp4a(zp0[8],  c2.x, a0);  b0 = __dp4a(zp1[8],  c2.x, b0);      \
    a1 = __dp4a(zp0[9],  c2.y, a1);  b1 = __dp4a(zp1[9],  c2.y, b1);      \
    a2 = __dp4a(zp0[10], c2.z, a2);  b2 = __dp4a(zp1[10], c2.z, b2);      \
    a3 = __dp4a(zp0[11], c2.w, a3);  b3 = __dp4a(zp1[11], c2.w, b3);      \
    a0 = __dp4a(zp0[12], c3.x, a0);  b0 = __dp4a(zp1[12], c3.x, b0);      \
    a1 = __dp4a(zp0[13], c3.y, a1);  b1 = __dp4a(zp1[13], c3.y, b1);      \
    a2 = __dp4a(zp0[14], c3.z, a2);  b2 = __dp4a(zp1[14], c3.z, b2);      \
    a3 = __dp4a(zp0[15], c3.w, a3);  b3 = __dp4a(zp1[15], c3.w, b3);      \
    (sOut0) = (a0 + a1) + (a2 + a3);                                      \
    (sOut1) = (b0 + b1) + (b2 + b3);                                      \
    twoCh = cs.y;                                                         \
} while (0)

// Exact fp32 distance from padded smem codebook (row = 272B, cn embedded).
// Bit-identical to the proven round-0 formula.
__device__ __forceinline__ float exact_dist_sm(const float* zr, float A,
                                               const char* __restrict__ smbase,
                                               int k) {
    const float4* cp = reinterpret_cast<const float4*>(smbase + SM_CBF + k * 272);
    float s0 = 0.f, s1 = 0.f, s2 = 0.f, s3 = 0.f;
#pragma unroll
    for (int i = 0; i < 16; ++i) {
        float4 c = cp[i];
        s0 = fmaf(zr[4 * i + 0], c.x, s0);
        s1 = fmaf(zr[4 * i + 1], c.y, s1);
        s2 = fmaf(zr[4 * i + 2], c.z, s2);
        s3 = fmaf(zr[4 * i + 3], c.w, s3);
    }
    float dot = __fadd_rn(__fadd_rn(s0, s1), __fadd_rn(s2, s3));
    float cn  = *reinterpret_cast<const float*>(smbase + SM_CBF + k * 272 + 264);
    return __fadd_rn(__fadd_rn(A, cn), -__fmul_rn(2.0f, dot));
}

// ---------------------------------------------------------------------------
// persistent fused VQ kernel. 384 thd (3 warps/SMSP), 2 tokens/thread,
// grid 148, atomic chunk stealing over 171 chunks of 768 tokens.
// ---------------------------------------------------------------------------
__global__ __launch_bounds__(THREADS_, 1)
void vq_kernel(const float* __restrict__ z,
               const float* __restrict__ cb,
               float* __restrict__ out_q,
               float* __restrict__ out_i,
               float* __restrict__ loss_ptr) {
    extern __shared__ char sm[];
    int4*     s_img  = reinterpret_cast<int4*>(sm + SM_IMG);
    unsigned* s_mask = reinterpret_cast<unsigned*>(sm + SM_MASK);
    float*    s_wsum = reinterpret_cast<float*>(sm + SM_WSUM);
    double*   s_rd   = reinterpret_cast<double*>(sm + SM_RD);
    int*      s_last = reinterpret_cast<int*>(sm + SM_LAST);
    int*      s_chnk = reinterpret_cast<int*>(sm + SM_CHNK);

    const int tid  = threadIdx.x;
    const int wid  = tid >> 5;
    const int lane = tid & 31;

    // ---- stage ONCE: int8 image; cbf rows (fp32 codebook + metadata) ----
    {
        const int4* src = reinterpret_cast<const int4*>(g_cbimg);
        for (int i = tid; i < K_ * 4; i += THREADS_) s_img[i] = src[i];
        const float4* cb4 = reinterpret_cast<const float4*>(cb);
        float4* dst = reinterpret_cast<float4*>(sm + SM_CBF);
        for (int i = tid; i < K_ * 16; i += THREADS_)
            dst[(i >> 4) * 17 + (i & 15)] = cb4[i];
        for (int i = tid; i < K_; i += THREADS_) {
            *reinterpret_cast<int2*>(sm + SM_CBF + i * 272 + 256) = g_cnsc[i];
            *reinterpret_cast<float*>(sm + SM_CBF + i * 272 + 264) = g_cbnorm[i];
        }
    }

    const float maxz = __uint_as_float(g_maxz_bits);
    const float inv_sz = (maxz > 0.0f) ? 127.0f / maxz : 0.0f;
    const float maxc  = __uint_as_float(g_maxc_bits);
    const float denom = 2.0f * (maxz * (1.0f / 127.0f)) * (maxc * (1.0f / 127.0f));
    const float slack_f = (denom > 0.0f) ? 2.0e-4f / denom : 4.0e9f;
    const int   slack   = (slack_f < 1.0e9f) ? ((int)slack_f + 2) : (1 << 27);

    // ---- persistent chunk-stealing loop ----
    for (;;) {
        __syncthreads();                      // protect s_mask/s_wsum reuse
        if (tid == 0) s_chnk[0] = (int)atomicAdd(&g_chunk, 1u);
        __syncthreads();
        const int chunk = s_chnk[0];
        if (chunk >= NCHUNK_) break;

        // token ids; token1 may be out of range in the last chunk
        const int n0 = chunk * CHTOK_ + tid;
        const int n1 = n0 + THREADS_;
        const bool v1 = (n1 < N_);
        const int n1c = v1 ? n1 : (N_ - 1);
        const size_t zoff0 = ((size_t)(n0 >> 12) << 18) + (size_t)(n0 & 4095);
        const size_t zoff1 = ((size_t)(n1c >> 12) << 18) + (size_t)(n1c & 4095);

        // ---- phase 1: stream both tokens (low reg footprint) ----
        float A0 = 0.0f, A1 = 0.0f;
        int zp0[16], zp1[16];
        int sabs0 = 0, sabs1 = 0;
#pragma unroll
        for (int j = 0; j < 16; ++j) {
            int p0 = 0, p1 = 0;
#pragma unroll
            for (int q = 0; q < 4; ++q) {
                float x0 = z[zoff0 + ((size_t)(4 * j + q) << 12)];
                float x1 = z[zoff1 + ((size_t)(4 * j + q) << 12)];
                A0 = fmaf(x0, x0, A0);  // canonical i = 0..63 order per token
                A1 = fmaf(x1, x1, A1);
                int b0 = min(127, max(-127, __float2int_rn(x0 * inv_sz)));
                int b1 = min(127, max(-127, __float2int_rn(x1 * inv_sz)));
                sabs0 += abs(b0);
                sabs1 += abs(b1);
                p0 |= ((-b0) & 0xFF) << (q * 8);
                p1 |= ((-b1) & 0xFF) << (q * 8);
            }
            zp0[j] = p0;
            zp1[j] = p1;
        }

        long long ml0 = (long long)sabs0 + 2LL * slack + 128;
        long long ml1 = (long long)sabs1 + 2LL * slack + 128;
        const int M0 = (int)((ml0 < (1LL << 29)) ? ml0 : (1LL << 29));
        const int M1 = (int)((ml1 < (1LL << 29)) ? ml1 : (1LL << 29));

        // ---- phase 2a: warm-up prepass (64 strided codes) ----
        int twoCh;
        int m00 = 0x7FFFFFFF, m01 = 0x7FFFFFFF;
#pragma unroll 4
        for (int j = 0; j < 64; ++j) {
            int s0, s1;
            DP4A_SCORE2(j * 8, s0, s1);
            m00 = min(m00, s0 + twoCh);
            m01 = min(m01, s1 + twoCh);
        }
        int thr0 = m00 + M0;
        int thr1 = m01 + M1;

        // ---- phase 2b: full dual-token screen -> bitmasks + summaries ----
        unsigned wnz0 = 0, wnz1 = 0;
#pragma unroll 1
        for (int m = 0; m < 16; ++m) {
            unsigned bits0 = 0, bits1 = 0;
#pragma unroll 4
            for (int j = 0; j < 32; ++j) {
                int s0, s1;
                DP4A_SCORE2(m * 32 + j, s0, s1);
                if (s0 <= thr0) bits0 |= (1u << j);
                thr0 = min(thr0, s0 + twoCh + M0);
                if (s1 <= thr1) bits1 |= (1u << j);
                thr1 = min(thr1, s1 + twoCh + M1);
            }
            s_mask[m * CHTOK_ + tid]            = bits0;
            s_mask[m * CHTOK_ + THREADS_ + tid] = bits1;
            if (bits0) wnz0 |= (1u << m);
            if (bits1) wnz1 |= (1u << m);
        }

        // ---- phases 3+4 per token: exact rescore, output, loss ----
        float acc = 0.0f;
#pragma unroll 1
        for (int t = 0; t < 2; ++t) {
            const size_t zoff = (t == 0) ? zoff0 : zoff1;
            const int tl      = (t == 0) ? tid : (THREADS_ + tid);
            unsigned wm       = (t == 0) ? wnz0 : wnz1;
            const float A     = (t == 0) ? A0 : A1;
            const bool valid  = (t == 0) ? true : v1;
            const int n       = (t == 0) ? n0 : n1c;

            float zr[D_];
#pragma unroll
            for (int i = 0; i < D_; ++i) zr[i] = z[zoff + ((size_t)i << 12)];

            float bd = 3.402823466e38f;
            int bestk = 0;
            while (wm) {                       // ascending words
                int m = __ffs(wm) - 1;
                wm &= wm - 1;
                unsigned bits = s_mask[m * CHTOK_ + tl];
                while (bits) {                 // ascending bits: first-min ties
                    int j = __ffs(bits) - 1;
                    bits &= bits - 1;
                    int k = m * 32 + j;
                    float dd = exact_dist_sm(zr, A, sm, k);
                    if (dd < bd) { bd = dd; bestk = k; }
                }
            }

            if (valid && out_i) out_i[n] = (float)bestk;

            const float4* qr =
                reinterpret_cast<const float4*>(sm + SM_CBF + bestk * 272);
            float* oq = (valid && out_q) ? (out_q + zoff) : nullptr;
#pragma unroll
            for (int j = 0; j < 16; ++j) {
                float4 qv = qr[j];
                float d0 = __fsub_rn(qv.x, zr[4 * j + 0]);
                float d1 = __fsub_rn(qv.y, zr[4 * j + 1]);
                float d2 = __fsub_rn(qv.z, zr[4 * j + 2]);
                float d3 = __fsub_rn(qv.w, zr[4 * j + 3]);
                if (oq) {
                    oq[(size_t)(4 * j + 0) << 12] = __fadd_rn(zr[4 * j + 0], d0);
                    oq[(size_t)(4 * j + 1) << 12] = __fadd_rn(zr[4 * j + 1], d1);
                    oq[(size_t)(4 * j + 2) << 12] = __fadd_rn(zr[4 * j + 2], d2);
                    oq[(size_t)(4 * j + 3) << 12] = __fadd_rn(zr[4 * j + 3], d3);
                }
                if (valid) {
                    acc = fmaf(d0, d0, acc);
                    acc = fmaf(d1, d1, acc);
                    acc = fmaf(d2, d2, acc);
                    acc = fmaf(d3, d3, acc);
                }
            }
        }

        // ---- per-chunk loss partial (deterministic per chunk) ----
#pragma unroll
        for (int o = 16; o > 0; o >>= 1)
            acc += __shfl_xor_sync(0xffffffffu, acc, o);
        if (lane == 0) s_wsum[wid] = acc;
        __syncthreads();
        if (tid == 0) {
            float s = 0.0f;
#pragma unroll
            for (int i = 0; i < 12; ++i) s += s_wsum[i];
            g_partial[chunk] = s;
        }
    }

    // ---- completion ticket ----
    if (tid == 0) {
        __threadfence();
        unsigned int ticket = atomicAdd(&g_count, 1u);
        s_last[0] = (ticket == (NBLK_ - 1)) ? 1 : 0;
    }
    __syncthreads();

    // ---- last block: deterministic finalize (256-slot tree; >=171 are 0) ----
    if (s_last[0]) {
        if (tid < 256) s_rd[tid] = (double)g_partial[tid];
        __syncthreads();
        for (int st = 128; st > 0; st >>= 1) {
            if (tid < st) s_rd[tid] += s_rd[tid + st];
            __syncthreads();
        }
        if (tid == 0) {
            if (loss_ptr) {
                float cl_ = (float)(s_rd[0] / (double)NQ_);
                loss_ptr[0] = __fadd_rn(cl_, __fmul_rn(0.25f, cl_));
            }
            g_count = 0;   // reset for next graph replay
            g_chunk = 0;
        }
    }
}

// ---------------------------------------------------------------------------
extern "C" void kernel_launch(void* const* d_in, const int* in_sizes, int n_in,
                              void* d_out, int out_size) {
    const float* z  = nullptr;
    const float* cb = nullptr;
    for (int i = 0; i < n_in; ++i) {
        if (in_sizes[i] == NQ_)          z  = (const float*)d_in[i];
        else if (in_sizes[i] == K_ * D_) cb = (const float*)d_in[i];
    }
    if (!z || !cb) return;

    float* out = (float*)d_out;
    float* loss_ptr = nullptr;
    float* q_ptr    = nullptr;
    float* i_ptr    = nullptr;

    if (out_size == 1 + NQ_ + N_) {
        loss_ptr = out; q_ptr = out + 1; i_ptr = out + 1 + NQ_;
    } else if (out_size == NQ_ + N_) {
        q_ptr = out; i_ptr = out + NQ_;
    } else if (out_size == NQ_) {
        q_ptr = out;
    } else if (out_size == N_) {
        i_ptr = out;
    } else if (out_size == 1) {
        loss_ptr = out;
    } else if (out_size > 1 + NQ_ + N_) {
        loss_ptr = out; q_ptr = out + 1; i_ptr = out + 1 + NQ_;
    }

    static bool attr_done = false;
    if (!attr_done) {
        cudaFuncSetAttribute(vq_kernel,
                             cudaFuncAttributeMaxDynamicSharedMemorySize,
                             SM_TOT);
        attr_done = true;
    }

    prep_z_kernel<<<512, 256>>>(z);
    prep_cb_kernel<<<1, 512>>>(cb);
    vq_kernel<<<NBLK_, THREADS_, SM_TOT>>>(z, cb, q_ptr, i_ptr, loss_ptr);
}

// round 16
// speedup vs baseline: 1.3233x; 1.3233x over previous
#include <cuda_runtime.h>
#include <cstdint>

// Problem constants (fixed by the reference)
#define B_ 32
#define D_ 64
#define T_ 4096
#define K_ 512
#define N_ (B_ * T_)        // 131072 tokens
#define NQ_ (B_ * D_ * T_)  // 8388608 quantized elements
#define NCHUNK_ 256         // 512 tokens per chunk
#define NBLK_ 148           // persistent blocks (1/SM)

// Scratch (device globals: no allocation allowed)
__device__ unsigned int g_maxz_bits;
__device__ unsigned int g_maxc_bits;
__device__ float        g_cbnorm[K_];
__device__ int2         g_cnsc[K_];            // (cn_int - ch, 2*ch), ch = ceil(sc/2)
__device__ __align__(16) int g_cbimg[K_ * 16];
__device__ float        g_partial[NCHUNK_];
__device__ unsigned int g_count;
__device__ unsigned int g_chunk;

// ---------------------------------------------------------------------------
// prep 0: global max |z|
// ---------------------------------------------------------------------------
__global__ void prep_z_kernel(const float* __restrict__ z) {
    const float4* z4 = reinterpret_cast<const float4*>(z);
    float m = 0.0f;
    for (int j = blockIdx.x * blockDim.x + threadIdx.x; j < NQ_ / 4;
         j += gridDim.x * blockDim.x) {
        float4 v = z4[j];
        m = fmaxf(m, fmaxf(fmaxf(fabsf(v.x), fabsf(v.y)),
                           fmaxf(fabsf(v.z), fabsf(v.w))));
    }
#pragma unroll
    for (int o = 16; o > 0; o >>= 1) m = fmaxf(m, __shfl_xor_sync(0xffffffffu, m, o));
    if ((threadIdx.x & 31) == 0) atomicMax(&g_maxz_bits, __float_as_uint(m));
}

// ---------------------------------------------------------------------------
// fused codebook prep: single block, 512 threads (one code each).
// norms in canonical fmaf order (proven rel_err = 0.0); maxc via shared-max
// (same value as atomicMax); then int8 image + (cn_int - ch, 2*ch).
// [validated rel_err = 0.0 in round 15]
// ---------------------------------------------------------------------------
__global__ void prep_cb_kernel(const float* __restrict__ cb) {
    __shared__ float s_red[512];
    const int k = threadIdx.x;                  // 0..511
    const float* r = cb + k * D_;
    float a = 0.0f, mx = 0.0f;
#pragma unroll
    for (int i = 0; i < D_; ++i) {
        a = fmaf(r[i], r[i], a);
        mx = fmaxf(mx, fabsf(r[i]));
    }
    g_cbnorm[k] = a;
    s_red[k] = mx;
    __syncthreads();
    for (int st = 256; st > 0; st >>= 1) {
        if (k < st) s_red[k] = fmaxf(s_red[k], s_red[k + st]);
        __syncthreads();
    }
    const float maxc = s_red[0];
    if (k == 0) g_maxc_bits = __float_as_uint(maxc);

    const float maxz = __uint_as_float(g_maxz_bits);
    const float inv_sc = (maxc > 0.0f) ? 127.0f / maxc : 0.0f;
    int sa = 0;
#pragma unroll
    for (int j = 0; j < 16; ++j) {
        int b0 = min(127, max(-127, __float2int_rn(r[4 * j + 0] * inv_sc)));
        int b1 = min(127, max(-127, __float2int_rn(r[4 * j + 1] * inv_sc)));
        int b2 = min(127, max(-127, __float2int_rn(r[4 * j + 2] * inv_sc)));
        int b3 = min(127, max(-127, __float2int_rn(r[4 * j + 3] * inv_sc)));
        sa += abs(b0) + abs(b1) + abs(b2) + abs(b3);
        g_cbimg[k * 16 + j] = (b0 & 0xFF) | ((b1 & 0xFF) << 8) |
                              ((b2 & 0xFF) << 16) | ((b3 & 0xFF) << 24);
    }
    const float denom = 2.0f * (maxz * (1.0f / 127.0f)) * (maxc * (1.0f / 127.0f));
    float v = (denom > 0.0f) ? a / denom : 0.0f;
    int cni = __float2int_rn(fminf(fmaxf(v, -2.0e9f), 2.0e9f));
    int ch  = (sa + 1) >> 1;                    // ceil(sc/2): conservative
    g_cnsc[k] = make_int2(cni - ch, 2 * ch);
}

// dual-token dp4a score block: s0/s1 = (cn_int - ch) - idot (seeded)
#define DP4A_SCORE2(k, sOut0, sOut1) do {                                 \
    int4 c0 = s_img[4 * (k) + 0], c1 = s_img[4 * (k) + 1];                \
    int4 c2 = s_img[4 * (k) + 2], c3 = s_img[4 * (k) + 3];                \
    int2 cs = s_cnsc[(k)];                                                \
    int a0 = cs.x, a1 = 0, a2 = 0, a3 = 0;                                \
    int b0 = cs.x, b1 = 0, b2 = 0, b3 = 0;                                \
    a0 = __dp4a(zp0[0],  c0.x, a0);  b0 = __dp4a(zp1[0],  c0.x, b0);      \
    a1 = __dp4a(zp0[1],  c0.y, a1);  b1 = __dp4a(zp1[1],  c0.y, b1);      \
    a2 = __dp4a(zp0[2],  c0.z, a2);  b2 = __dp4a(zp1[2],  c0.z, b2);      \
    a3 = __dp4a(zp0[3],  c0.w, a3);  b3 = __dp4a(zp1[3],  c0.w, b3);      \
    a0 = __dp4a(zp0[4],  c1.x, a0);  b0 = __dp4a(zp1[4],  c1.x, b0);      \
    a1 = __dp4a(zp0[5],  c1.y, a1);  b1 = __dp4a(zp1[5],  c1.y, b1);      \
    a2 = __dp4a(zp0[6],  c1.z, a2);  b2 = __dp4a(zp1[6],  c1.z, b2);      \
    a3 = __dp4a(zp0[7],  c1.w, a3);  b3 = __dp4a(zp1[7],  c1.w, b3);      \
    a0 = __dp4a(zp0[8],  c2.x, a0);  b0 = __dp4a(zp1[8],  c2.x, b0);      \
    a1 = __dp4a(zp0[9],  c2.y, a1);  b1 = __dp4a(zp1[9],  c2.y, b1);      \
    a2 = __dp4a(zp0[10], c2.z, a2);  b2 = __dp4a(zp1[10], c2.z, b2);      \
    a3 = __dp4a(zp0[11], c2.w, a3);  b3 = __dp4a(zp1[11], c2.w, b3);      \
    a0 = __dp4a(zp0[12], c3.x, a0);  b0 = __dp4a(zp1[12], c3.x, b0);      \
    a1 = __dp4a(zp0[13], c3.y, a1);  b1 = __dp4a(zp1[13], c3.y, b1);      \
    a2 = __dp4a(zp0[14], c3.z, a2);  b2 = __dp4a(zp1[14], c3.z, b2);      \
    a3 = __dp4a(zp0[15], c3.w, a3);  b3 = __dp4a(zp1[15], c3.w, b3);      \
    (sOut0) = (a0 + a1) + (a2 + a3);                                      \
    (sOut1) = (b0 + b1) + (b2 + b3);                                      \
    twoCh = cs.y;                                                         \
} while (0)

// ---------------------------------------------------------------------------
// Exact fp32 distance from PADDED smem codebook (row stride 17 float4 units).
// Bit-identical to the proven round-0 formula.
// ---------------------------------------------------------------------------
__device__ __forceinline__ float exact_dist_sm(const float* zr, float A,
                                               const float4* __restrict__ cbf,
                                               const float* __restrict__ cnf,
                                               int k) {
    const float4* cp = cbf + k * 17;
    float s0 = 0.f, s1 = 0.f, s2 = 0.f, s3 = 0.f;
#pragma unroll
    for (int i = 0; i < 16; ++i) {
        float4 c = cp[i];
        s0 = fmaf(zr[4 * i + 0], c.x, s0);
        s1 = fmaf(zr[4 * i + 1], c.y, s1);
        s2 = fmaf(zr[4 * i + 2], c.z, s2);
        s3 = fmaf(zr[4 * i + 3], c.w, s3);
    }
    float dot = __fadd_rn(__fadd_rn(s0, s1), __fadd_rn(s2, s3));
    return __fadd_rn(__fadd_rn(A, cnf[k]), -__fmul_rn(2.0f, dot));
}

// ---------------------------------------------------------------------------
// persistent fused VQ kernel. 256 thd, 2 tokens/thread, grid 148 (1/SM),
// atomic chunk stealing over 256 chunks of 512 tokens. [round-14 verbatim]
// ---------------------------------------------------------------------------
#define SM_IMG   0                            // 2048 int4        =  32768
#define SM_CNSC  32768                        // 512 int2         =   4096
#define SM_CNF   36864                        // 512 float        =   2048
#define SM_CBF   38912                        // 512*17 float4    = 139264
#define SM_MASK  178176                       // 16*512 uint      =  32768
#define SM_WSUM  210944                       // 8 float (+pad)   =     64
#define SM_RD    211008                       // 256 double       =   2048
#define SM_LAST  213056                       // int              =      4
#define SM_CHNK  213060                       // int (+pad)       =     12
#define SM_TOT   213072

__global__ __launch_bounds__(256, 1)
void vq_kernel(const float* __restrict__ z,
               const float* __restrict__ cb,
               float* __restrict__ out_q,
               float* __restrict__ out_i,
               float* __restrict__ loss_ptr) {
    extern __shared__ char sm[];
    int4*     s_img  = reinterpret_cast<int4*>(sm + SM_IMG);
    int2*     s_cnsc = reinterpret_cast<int2*>(sm + SM_CNSC);
    float*    s_cnf  = reinterpret_cast<float*>(sm + SM_CNF);
    float4*   s_cbf  = reinterpret_cast<float4*>(sm + SM_CBF);
    unsigned* s_mask = reinterpret_cast<unsigned*>(sm + SM_MASK);
    float*    s_wsum = reinterpret_cast<float*>(sm + SM_WSUM);
    double*   s_rd   = reinterpret_cast<double*>(sm + SM_RD);
    int*      s_last = reinterpret_cast<int*>(sm + SM_LAST);
    int*      s_chnk = reinterpret_cast<int*>(sm + SM_CHNK);

    const int tid  = threadIdx.x;
    const int wid  = tid >> 5;
    const int lane = tid & 31;

    // ---- stage ONCE: int8 image, (cnlo,2ch), fp32 cn, padded fp32 codebook
    {
        const int4* src = reinterpret_cast<const int4*>(g_cbimg);
#pragma unroll
        for (int i = tid; i < K_ * 4; i += 256) s_img[i] = src[i];
#pragma unroll
        for (int i = tid; i < K_; i += 256) {
            s_cnsc[i] = g_cnsc[i];
            s_cnf[i]  = g_cbnorm[i];
        }
        const float4* cb4 = reinterpret_cast<const float4*>(cb);
#pragma unroll
        for (int i = tid; i < K_ * 16; i += 256)
            s_cbf[(i >> 4) * 17 + (i & 15)] = cb4[i];
    }

    const float maxz = __uint_as_float(g_maxz_bits);
    const float inv_sz = (maxz > 0.0f) ? 127.0f / maxz : 0.0f;
    const float maxc  = __uint_as_float(g_maxc_bits);
    const float denom = 2.0f * (maxz * (1.0f / 127.0f)) * (maxc * (1.0f / 127.0f));
    const float slack_f = (denom > 0.0f) ? 2.0e-4f / denom : 4.0e9f;
    const int   slack   = (slack_f < 1.0e9f) ? ((int)slack_f + 2) : (1 << 27);

    // ---- persistent chunk-stealing loop ----
    for (;;) {
        __syncthreads();                      // protect s_mask/s_wsum reuse
        if (tid == 0) s_chnk[0] = (int)atomicAdd(&g_chunk, 1u);
        __syncthreads();
        const int chunk = s_chnk[0];
        if (chunk >= NCHUNK_) break;

        // ---- phase 1: stream both tokens (low reg footprint) ----
        const int nbase = chunk * 512;
        const int bidx  = nbase >> 12;
        const float* zb = z + ((size_t)bidx << 18);
        const int t0 = (nbase & 4095) + tid;   // token 0 column
        const int t1 = t0 + 256;               // token 1 column

        float A0 = 0.0f, A1 = 0.0f;
        int zp0[16], zp1[16];
        int sabs0 = 0, sabs1 = 0;
#pragma unroll
        for (int j = 0; j < 16; ++j) {
            int p0 = 0, p1 = 0;
#pragma unroll
            for (int q = 0; q < 4; ++q) {
                float x0 = zb[((size_t)(4 * j + q) << 12) + t0];
                float x1 = zb[((size_t)(4 * j + q) << 12) + t1];
                A0 = fmaf(x0, x0, A0);  // canonical i = 0..63 order per token
                A1 = fmaf(x1, x1, A1);
                int b0 = min(127, max(-127, __float2int_rn(x0 * inv_sz)));
                int b1 = min(127, max(-127, __float2int_rn(x1 * inv_sz)));
                sabs0 += abs(b0);
                sabs1 += abs(b1);
                p0 |= ((-b0) & 0xFF) << (q * 8);
                p1 |= ((-b1) & 0xFF) << (q * 8);
            }
            zp0[j] = p0;
            zp1[j] = p1;
        }

        long long ml0 = (long long)sabs0 + 2LL * slack + 128;
        long long ml1 = (long long)sabs1 + 2LL * slack + 128;
        const int M0 = (int)((ml0 < (1LL << 29)) ? ml0 : (1LL << 29));
        const int M1 = (int)((ml1 < (1LL << 29)) ? ml1 : (1LL << 29));

        // ---- phase 2a: warm-up prepass (64 strided codes) ----
        int twoCh;
        int m00 = 0x7FFFFFFF, m01 = 0x7FFFFFFF;
#pragma unroll 4
        for (int j = 0; j < 64; ++j) {
            int s0, s1;
            DP4A_SCORE2(j * 8, s0, s1);
            m00 = min(m00, s0 + twoCh);
            m01 = min(m01, s1 + twoCh);
        }
        int thr0 = m00 + M0;
        int thr1 = m01 + M1;

        // ---- phase 2b: full dual-token screen -> bitmasks + summaries ----
        unsigned wnz0 = 0, wnz1 = 0;
#pragma unroll 1
        for (int m = 0; m < 16; ++m) {
            unsigned bits0 = 0, bits1 = 0;
#pragma unroll 4
            for (int j = 0; j < 32; ++j) {
                int s0, s1;
                DP4A_SCORE2(m * 32 + j, s0, s1);
                if (s0 <= thr0) bits0 |= (1u << j);
                thr0 = min(thr0, s0 + twoCh + M0);
                if (s1 <= thr1) bits1 |= (1u << j);
                thr1 = min(thr1, s1 + twoCh + M1);
            }
            s_mask[m * 512 + tid]       = bits0;
            s_mask[m * 512 + 256 + tid] = bits1;
            if (bits0) wnz0 |= (1u << m);
            if (bits1) wnz1 |= (1u << m);
        }

        // ---- phases 3+4 per token: exact rescore, output, loss ----
        float acc = 0.0f;
#pragma unroll 1
        for (int t = 0; t < 2; ++t) {
            const int tcol = (t == 0) ? t0 : t1;
            const int tl   = (t == 0) ? tid : (256 + tid);
            unsigned wm    = (t == 0) ? wnz0 : wnz1;
            const float A  = (t == 0) ? A0 : A1;
            const float* zc = zb + tcol;

            float zr[D_];
#pragma unroll
            for (int i = 0; i < D_; ++i) zr[i] = zc[(size_t)i << 12];

            float bd = 3.402823466e38f;
            int bestk = 0;
            while (wm) {                       // ascending words
                int m = __ffs(wm) - 1;
                wm &= wm - 1;
                unsigned bits = s_mask[m * 512 + tl];
                while (bits) {                 // ascending bits: first-min ties
                    int j = __ffs(bits) - 1;
                    bits &= bits - 1;
                    int k = m * 32 + j;
                    float dd = exact_dist_sm(zr, A, s_cbf, s_cnf, k);
                    if (dd < bd) { bd = dd; bestk = k; }
                }
            }

            const int n = (bidx << 12) + tcol;
            if (out_i) out_i[n] = (float)bestk;

            const float4* qr = s_cbf + bestk * 17;
            float* oq = out_q ? out_q + ((size_t)bidx << 18) + tcol : nullptr;
#pragma unroll
            for (int j = 0; j < 16; ++j) {
                float4 qv = qr[j];
                float d0 = __fsub_rn(qv.x, zr[4 * j + 0]);
                float d1 = __fsub_rn(qv.y, zr[4 * j + 1]);
                float d2 = __fsub_rn(qv.z, zr[4 * j + 2]);
                float d3 = __fsub_rn(qv.w, zr[4 * j + 3]);
                if (oq) {
                    oq[(size_t)(4 * j + 0) << 12] = __fadd_rn(zr[4 * j + 0], d0);
                    oq[(size_t)(4 * j + 1) << 12] = __fadd_rn(zr[4 * j + 1], d1);
                    oq[(size_t)(4 * j + 2) << 12] = __fadd_rn(zr[4 * j + 2], d2);
                    oq[(size_t)(4 * j + 3) << 12] = __fadd_rn(zr[4 * j + 3], d3);
                }
                acc = fmaf(d0, d0, acc);
                acc = fmaf(d1, d1, acc);
                acc = fmaf(d2, d2, acc);
                acc = fmaf(d3, d3, acc);
            }
        }

        // ---- per-chunk loss partial (deterministic per chunk) ----
#pragma unroll
        for (int o = 16; o > 0; o >>= 1)
            acc += __shfl_xor_sync(0xffffffffu, acc, o);
        if (lane == 0) s_wsum[wid] = acc;
        __syncthreads();
        if (tid == 0) {
            float s = 0.0f;
#pragma unroll
            for (int i = 0; i < 8; ++i) s += s_wsum[i];
            g_partial[chunk] = s;
        }
    }

    // ---- completion ticket ----
    if (tid == 0) {
        __threadfence();
        unsigned int ticket = atomicAdd(&g_count, 1u);
        s_last[0] = (ticket == (NBLK_ - 1)) ? 1 : 0;
    }
    __syncthreads();

    // ---- last block: deterministic finalize ----
    if (s_last[0]) {
        if (tid < 256) s_rd[tid] = (double)g_partial[tid];
        __syncthreads();
        for (int st = 128; st > 0; st >>= 1) {
            if (tid < st) s_rd[tid] += s_rd[tid + st];
            __syncthreads();
        }
        if (tid == 0) {
            if (loss_ptr) {
                float cl_ = (float)(s_rd[0] / (double)NQ_);
                loss_ptr[0] = __fadd_rn(cl_, __fmul_rn(0.25f, cl_));
            }
            g_count = 0;   // reset for next graph replay
            g_chunk = 0;
        }
    }
}

// ---------------------------------------------------------------------------
extern "C" void kernel_launch(void* const* d_in, const int* in_sizes, int n_in,
                              void* d_out, int out_size) {
    const float* z  = nullptr;
    const float* cb = nullptr;
    for (int i = 0; i < n_in; ++i) {
        if (in_sizes[i] == NQ_)          z  = (const float*)d_in[i];
        else if (in_sizes[i] == K_ * D_) cb = (const float*)d_in[i];
    }
    if (!z || !cb) return;

    float* out = (float*)d_out;
    float* loss_ptr = nullptr;
    float* q_ptr    = nullptr;
    float* i_ptr    = nullptr;

    if (out_size == 1 + NQ_ + N_) {
        loss_ptr = out; q_ptr = out + 1; i_ptr = out + 1 + NQ_;
    } else if (out_size == NQ_ + N_) {
        q_ptr = out; i_ptr = out + NQ_;
    } else if (out_size == NQ_) {
        q_ptr = out;
    } else if (out_size == N_) {
        i_ptr = out;
    } else if (out_size == 1) {
        loss_ptr = out;
    } else if (out_size > 1 + NQ_ + N_) {
        loss_ptr = out; q_ptr = out + 1; i_ptr = out + 1 + NQ_;
    }

    static bool attr_done = false;
    if (!attr_done) {
        cudaFuncSetAttribute(vq_kernel,
                             cudaFuncAttributeMaxDynamicSharedMemorySize,
                             SM_TOT);
        attr_done = true;
    }

    prep_z_kernel<<<512, 256>>>(z);
    prep_cb_kernel<<<1, 512>>>(cb);
    vq_kernel<<<NBLK_, 256, SM_TOT>>>(z, cb, q_ptr, i_ptr, loss_ptr);
}